// round 3
// baseline (speedup 1.0000x reference)
#include <cuda_runtime.h>
#include <cstdint>

// Problem constants
#define BB   8
#define CC   256
#define HH   64
#define WW   96
#define ND   21
#define NDD  441
#define MAXD 20

// Tiling
#define GDY  7          // dy per block (3 blocks cover 21)
#define RD   7          // dx per thread
#define RX   8          // x per thread
#define CK   8          // channels per chunk
#define NC   (CC/CK)    // 32 chunks
#define BSTR 140        // padded in2 row stride (floats, 16B-aligned rows)
#define NACT 252
#define NTH  256

#define A_ELEMS (CK*WW)           // 768 floats per stage
#define B_ELEMS (CK*GDY*BSTR)     // 7840 floats per stage
#define STAGE_ELEMS (A_ELEMS + B_ELEMS)    // 8608
#define SMEM_FLOATS (2*STAGE_ELEMS)        // 17216 -> 68864 bytes
#define SMEM_BYTES (SMEM_FLOATS*4)

typedef unsigned long long u64t;

__device__ __forceinline__ void cp_async16(uint32_t saddr, const void* gptr) {
    asm volatile("cp.async.ca.shared.global [%0], [%1], 16;\n" :: "r"(saddr), "l"(gptr));
}
__device__ __forceinline__ void cp_commit() {
    asm volatile("cp.async.commit_group;\n" ::: "memory");
}
template<int N> __device__ __forceinline__ void cp_wait() {
    asm volatile("cp.async.wait_group %0;\n" :: "n"(N) : "memory");
}
__device__ __forceinline__ void fma_f32x2(u64t& d, u64t a, u64t b) {
    asm("fma.rn.f32x2 %0, %1, %2, %0;" : "+l"(d) : "l"(a), "l"(b));
}

__global__ __launch_bounds__(NTH, 2)
void corr_f32x2_kernel(const float* __restrict__ in1,
                       const float* __restrict__ in2,
                       float* __restrict__ out)
{
    extern __shared__ float sm[];

    // block decode: bid = ((b*HH + y)*3 + dyG)
    int bid = blockIdx.x;
    int dyG = bid % 3;
    int y   = (bid / 3) % HH;
    int b   = bid / (3 * HH);
    int jdyBase = dyG * GDY;

    int tid  = threadIdx.x;
    int w    = tid >> 5;          // staging warp = channel within chunk
    int lane = tid & 31;
    bool active = (tid < NACT);

    // compute-thread decode: tid = gx*21 + (gdy*3 + gdx)
    int gx  = tid / (GDY * 3);
    int rem = tid % (GDY * 3);
    int gdy = rem / 3;
    int gdx = rem % 3;
    int xbase   = gx * RX;
    int jdxBase = gdx * RD;
    int off     = xbase + 2 * jdxBase;   // even -> 8B-aligned reads

    // valid in2 rows for this block's 7 dy values
    int  row2v[GDY];
    bool rowok[GDY];
    #pragma unroll
    for (int g = 0; g < GDY; g++) {
        int r = y - MAXD + 2 * (jdyBase + g);
        row2v[g] = r;
        rowok[g] = (unsigned)r < (unsigned)HH;
    }

    const size_t HW = (size_t)HH * WW;

    // zero all smem once (pads + OOB rows stay zero forever)
    for (int i = tid; i < SMEM_FLOATS; i += NTH) sm[i] = 0.0f;
    __syncthreads();

    // per-warp staging base pointers (channel stride = CK per chunk)
    const float* g1row = in1 + ((size_t)b * CC + w) * HW + (size_t)y * WW;
    const float* g2chan = in2 + ((size_t)b * CC + w) * HW;

    // ---- staging lambda: chunk k into stage s ----
    auto stage = [&](int k, int s) {
        if (lane < 24) {
            float* abase = sm + s * STAGE_ELEMS + w * WW;
            const float* p1 = g1row + (size_t)k * CK * HW;
            cp_async16((uint32_t)__cvta_generic_to_shared(abase + lane * 4), p1 + lane * 4);
            float* bbase = sm + s * STAGE_ELEMS + A_ELEMS + w * (GDY * BSTR);
            const float* p2 = g2chan + (size_t)k * CK * HW;
            #pragma unroll
            for (int g = 0; g < GDY; g++) {
                if (rowok[g]) {
                    cp_async16((uint32_t)__cvta_generic_to_shared(bbase + g * BSTR + MAXD + lane * 4),
                               p2 + (size_t)row2v[g] * WW + lane * 4);
                }
            }
        }
    };

    u64t acc[RD][RX/2];
    #pragma unroll
    for (int t = 0; t < RD; t++)
        #pragma unroll
        for (int ip = 0; ip < RX/2; ip++)
            acc[t][ip] = 0ull;

    // prologue
    stage(0, 0);
    cp_commit();

    #pragma unroll 1
    for (int k = 0; k < NC; k++) {
        int s = k & 1;
        if (k + 1 < NC) {
            stage(k + 1, s ^ 1);
            cp_commit();
            cp_wait<1>();
        } else {
            cp_wait<0>();
        }
        __syncthreads();

        if (active) {
            const float* abuf = sm + s * STAGE_ELEMS;
            const float* bbuf = abuf + A_ELEMS;
            #pragma unroll
            for (int c = 0; c < CK; c++) {
                const u64t* ap = (const u64t*)(abuf + c * WW + xbase);
                u64t a2[RX/2];
                #pragma unroll
                for (int ip = 0; ip < RX/2; ip++) a2[ip] = ap[ip];

                const u64t* bp = (const u64t*)(bbuf + c * (GDY * BSTR) + gdy * BSTR + off);
                u64t b2[RX/2 + RD - 1];   // 10
                #pragma unroll
                for (int m = 0; m < RX/2 + RD - 1; m++) b2[m] = bp[m];

                #pragma unroll
                for (int t = 0; t < RD; t++)
                    #pragma unroll
                    for (int ip = 0; ip < RX/2; ip++)
                        fma_f32x2(acc[t][ip], a2[ip], b2[ip + t]);
            }
        }
        __syncthreads();
    }

    if (active) {
        const float scale = 1.0f / (float)CC;
        int jdy = jdyBase + gdy;
        #pragma unroll
        for (int t = 0; t < RD; t++) {
            int d = jdy * ND + (jdxBase + t);
            size_t obase = (((size_t)b * NDD + d) * HH + y) * WW + xbase;
            float2* op = (float2*)(out + obase);
            #pragma unroll
            for (int ip = 0; ip < RX/2; ip++) {
                u64t v = acc[t][ip];
                float lo = __uint_as_float((unsigned)(v & 0xffffffffull));
                float hi = __uint_as_float((unsigned)(v >> 32));
                op[ip] = make_float2(lo * scale, hi * scale);
            }
        }
    }
}

extern "C" void kernel_launch(void* const* d_in, const int* in_sizes, int n_in,
                              void* d_out, int out_size)
{
    const float* in1 = (const float*)d_in[0];
    const float* in2 = (const float*)d_in[1];
    float* out = (float*)d_out;

    cudaFuncSetAttribute(corr_f32x2_kernel,
                         cudaFuncAttributeMaxDynamicSharedMemorySize, SMEM_BYTES);

    dim3 grid(BB * HH * 3);
    dim3 block(NTH);
    corr_f32x2_kernel<<<grid, block, SMEM_BYTES>>>(in1, in2, out);
}

// round 5
// speedup vs baseline: 2.8137x; 2.8137x over previous
#include <cuda_runtime.h>
#include <cuda_fp16.h>
#include <cstdint>

// ---------------- problem constants ----------------
#define BB   8
#define CCH  256
#define HH   64
#define WW   96
#define ND   21
#define NDD  441
#define HW_  6144            // HH*WW

// ---------------- fp16 swizzled images ----------------
// layout: element (row r, k) at  r*512 + ((k>>3 ^ (r&7))*16) + (k&7)*2
#define A_IMG 49152          // 96 rows * 512 B
#define B_IMG 69632          // 136 rows * 512 B

__device__ __align__(16) unsigned char g_A[(size_t)BB * HH * A_IMG];  // 25.2 MB
__device__ __align__(16) unsigned char g_B[(size_t)BB * HH * B_IMG];  // 35.7 MB

// ---------------- main-kernel smem layout (relative to 1024-aligned base) ----
#define SM_A    0
#define SM_B0   49152
#define SM_B1   118784
#define SM_RED  188416       // 6 m-tiles * 28 regs * 32 lanes * 4B = 21504
#define SMEM_REQ (209920 + 1024)

// ---------------- ptx helpers (all baseline PTX, no sm_103a features) -------
__device__ __forceinline__ void cp_async16(uint32_t s, const void* g) {
    asm volatile("cp.async.cg.shared.global [%0], [%1], 16;\n" :: "r"(s), "l"(g));
}
__device__ __forceinline__ void cp_commit() {
    asm volatile("cp.async.commit_group;" ::: "memory");
}
template<int N> __device__ __forceinline__ void cp_wait() {
    asm volatile("cp.async.wait_group %0;" :: "n"(N) : "memory");
}
__device__ __forceinline__ void ldsm4(uint32_t* r, uint32_t a) {
    asm volatile("ldmatrix.sync.aligned.m8n8.x4.shared.b16 {%0,%1,%2,%3}, [%4];"
                 : "=r"(r[0]), "=r"(r[1]), "=r"(r[2]), "=r"(r[3]) : "r"(a));
}
__device__ __forceinline__ void ldsm2(uint32_t* r, uint32_t a) {
    asm volatile("ldmatrix.sync.aligned.m8n8.x2.shared.b16 {%0,%1}, [%2];"
                 : "=r"(r[0]), "=r"(r[1]) : "r"(a));
}
__device__ __forceinline__ void mma16816(float* d, const uint32_t* a, const uint32_t* b) {
    asm volatile("mma.sync.aligned.m16n8k16.row.col.f32.f16.f16.f32 "
                 "{%0,%1,%2,%3}, {%4,%5,%6,%7}, {%8,%9}, {%0,%1,%2,%3};"
                 : "+f"(d[0]), "+f"(d[1]), "+f"(d[2]), "+f"(d[3])
                 : "r"(a[0]), "r"(a[1]), "r"(a[2]), "r"(a[3]), "r"(b[0]), "r"(b[1]));
}

// ================= prepass A: fp16 swizzled image of in1 rows =================
__global__ __launch_bounds__(128) void prep_a(const float* __restrict__ in1) {
    __shared__ float raw[64][97];
    int bid = blockIdx.x;
    int y = bid & 63, b = bid >> 6;
    unsigned char* img = g_A + (size_t)bid * A_IMG;
    int tid = threadIdx.x;

    for (int q = 0; q < 4; q++) {               // 64-channel chunks
        __syncthreads();
        for (int i = tid; i < 64 * 96; i += 128) {
            int c = i / 96, x = i - c * 96;
            raw[c][x] = in1[(((size_t)b * CCH + q * 64 + c) * HH + y) * WW + x];
        }
        __syncthreads();
        for (int u = tid; u < 768; u += 128) {  // 96 rows * 8 k-units
            int r = u >> 3, kl = u & 7;
            int ku = q * 8 + kl;
            uint32_t h[4];
            #pragma unroll
            for (int j = 0; j < 4; j++) {
                __half2 v = __floats2half2_rn(raw[kl * 8 + 2 * j][r],
                                              raw[kl * 8 + 2 * j + 1][r]);
                h[j] = *reinterpret_cast<uint32_t*>(&v);
            }
            int off = r * 512 + ((ku ^ (r & 7)) << 4);
            *reinterpret_cast<uint4*>(img + off) = make_uint4(h[0], h[1], h[2], h[3]);
        }
    }
}

// ================= prepass B: padded fp16 swizzled image of in2 rows ==========
__global__ __launch_bounds__(128) void prep_b(const float* __restrict__ in2) {
    __shared__ float raw[64][97];
    int bid = blockIdx.x;
    int y2 = bid & 63, b = bid >> 6;
    unsigned char* img = g_B + (size_t)bid * B_IMG;
    int tid = threadIdx.x;

    for (int q = 0; q < 4; q++) {
        __syncthreads();
        for (int i = tid; i < 64 * 96; i += 128) {
            int c = i / 96, x = i - c * 96;
            raw[c][x] = in2[(((size_t)b * CCH + q * 64 + c) * HH + y2) * WW + x];
        }
        __syncthreads();
        for (int u = tid; u < 1088; u += 128) {  // 136 rows * 8 k-units
            int r = u >> 3, kl = u & 7;          // r = x' slot 0..135
            int ku = q * 8 + kl;
            int xs = r - 20;
            bool ok = (unsigned)xs < 96u;
            uint32_t h[4];
            #pragma unroll
            for (int j = 0; j < 4; j++) {
                float lo = ok ? raw[kl * 8 + 2 * j][xs]     : 0.0f;
                float hi = ok ? raw[kl * 8 + 2 * j + 1][xs] : 0.0f;
                __half2 v = __floats2half2_rn(lo, hi);
                h[j] = *reinterpret_cast<uint32_t*>(&v);
            }
            int off = r * 512 + ((ku ^ (r & 7)) << 4);
            *reinterpret_cast<uint4*>(img + off) = make_uint4(h[0], h[1], h[2], h[3]);
        }
    }
}

// ================= main kernel: banded HMMA GEMM per (b,y) ====================
__global__ __launch_bounds__(384, 1) void corr_hmma(float* __restrict__ out) {
    extern __shared__ __align__(16) unsigned char smraw[];
    uint32_t SB = ((uint32_t)__cvta_generic_to_shared(smraw) + 1023u) & ~1023u;

    int bid = blockIdx.x;
    int y = bid & 63, b = bid >> 6;
    int tid = threadIdx.x, w = tid >> 5, lane = tid & 31;
    int mt = w % 6;          // m16 tile: x in [16mt, 16mt+16)
    int kh = w / 6;          // k-half: channels [128kh, 128kh+128)
    int g = lane >> 2, t = lane & 3;

    // ---- valid dy list ----
    int vlist[ND]; int nv = 0;
    #pragma unroll
    for (int d = 0; d < ND; d++) {
        int y2 = y - 20 + 2 * d;
        if ((unsigned)y2 < (unsigned)HH) vlist[nv++] = d;
    }

    // ---- prologue staging: A (full) + B row vlist[0] ----
    const unsigned char* imgA = g_A + (size_t)bid * A_IMG;
    for (int i = tid; i < 3072; i += 384)
        cp_async16(SB + SM_A + i * 16, imgA + i * 16);
    {
        int y2 = y - 20 + 2 * vlist[0];
        const unsigned char* img = g_B + (size_t)(b * HH + y2) * B_IMG;
        for (int i = tid; i < 4352; i += 384)
            cp_async16(SB + SM_B0 + i * 16, img + i * 16);
    }
    cp_commit();

    // ---- zero invalid-dy output slices (overlaps prologue cp.async) ----
    #pragma unroll 1
    for (int d = 0; d < ND; d++) {
        int y2 = y - 20 + 2 * d;
        if ((unsigned)y2 >= (unsigned)HH) {
            for (int i = tid; i < ND * WW; i += 384) {
                int dj = i / WW, x = i - dj * WW;
                out[(((size_t)b * NDD + d * ND + dj) * HH + y) * WW + x] = 0.0f;
            }
        }
    }

    // ---- per-lane ldmatrix address precompute ----
    uint32_t arow  = 16u * mt + (lane & 7) + 8u * ((lane >> 3) & 1);
    uint32_t abase = SB + SM_A + arow * 512u;
    uint32_t ar7   = arow & 7u;
    uint32_t akoff = (uint32_t)(lane >> 4);           // +0 / +1 k-unit
    uint32_t bkoff = (uint32_t)((lane >> 3) & 1);

    uint32_t brow512[4], br7[4];
    #pragma unroll
    for (int p = 0; p < 3; p++) {
        uint32_t br = 8u * (2u * mt + 2u * p + (uint32_t)(lane >> 4)) + (lane & 7);
        brow512[p] = br * 512u;
        br7[p] = br & 7u;
    }
    {
        uint32_t br = 8u * (2u * mt + 6u) + (lane & 7);
        brow512[3] = br * 512u;
        br7[3] = br & 7u;
    }

    uint32_t redb = SB + SM_RED + (uint32_t)mt * 3584u;
    const float scale = 1.0f / 256.0f;

    // ---- main loop over valid dy rows ----
    #pragma unroll 1
    for (int vi = 0; vi < nv; vi++) {
        // stage next row into other buffer; wait for current
        if (vi + 1 < nv) {
            int y2n = y - 20 + 2 * vlist[vi + 1];
            const unsigned char* img = g_B + (size_t)(b * HH + y2n) * B_IMG;
            uint32_t dst = SB + (((vi + 1) & 1) ? SM_B1 : SM_B0);
            for (int i = tid; i < 4352; i += 384)
                cp_async16(dst + i * 16, img + i * 16);
            cp_commit();
            cp_wait<1>();
        } else {
            cp_wait<0>();
        }
        __syncthreads();

        uint32_t SBB = SB + ((vi & 1) ? SM_B1 : SM_B0);

        float acc[7][4];
        #pragma unroll
        for (int jj = 0; jj < 7; jj++)
            #pragma unroll
            for (int r = 0; r < 4; r++) acc[jj][r] = 0.0f;

        #pragma unroll
        for (int ks = 0; ks < 8; ks++) {
            uint32_t aku = (uint32_t)(kh * 16 + 2 * ks) + akoff;
            uint32_t a[4];
            ldsm4(a, abase + ((aku ^ ar7) << 4));

            uint32_t bku = (uint32_t)(kh * 16 + 2 * ks) + bkoff;
            uint32_t bfr[7][2];
            #pragma unroll
            for (int p = 0; p < 3; p++)
                ldsm4(&bfr[2 * p][0], SBB + brow512[p] + ((bku ^ br7[p]) << 4));
            ldsm2(&bfr[6][0], SBB + brow512[3] + ((bku ^ br7[3]) << 4));

            #pragma unroll
            for (int jj = 0; jj < 7; jj++)
                mma16816(acc[jj], a, bfr[jj]);
        }

        // ---- split-K reduce through smem scratch ----
        if (kh == 0) {
            #pragma unroll
            for (int jj = 0; jj < 7; jj++)
                #pragma unroll
                for (int r = 0; r < 4; r++)
                    asm volatile("st.shared.f32 [%0], %1;"
                                 :: "r"(redb + (uint32_t)((jj * 4 + r) * 128 + lane * 4)),
                                    "f"(acc[jj][r]) : "memory");
        }
        __syncthreads();
        if (kh == 1) {
            #pragma unroll
            for (int jj = 0; jj < 7; jj++)
                #pragma unroll
                for (int r = 0; r < 4; r++) {
                    float p;
                    asm volatile("ld.shared.f32 %0, [%1];"
                                 : "=f"(p)
                                 : "r"(redb + (uint32_t)((jj * 4 + r) * 128 + lane * 4)));
                    acc[jj][r] += p;
                }

            // ---- band extraction epilogue ----
            int dyi = vlist[vi];
            size_t obase = (((size_t)b * NDD + dyi * ND) * HH + y) * WW;
            #pragma unroll
            for (int jj = 0; jj < 7; jj++) {
                #pragma unroll
                for (int rh = 0; rh < 2; rh++) {
                    int di = 4 * jj - 4 * rh + t - (g >> 1);
                    float v = (g & 1) ? acc[jj][2 * rh + 1] : acc[jj][2 * rh];
                    int x = 16 * mt + g + 8 * rh;
                    if ((unsigned)di <= 20u)
                        out[obase + (size_t)di * HW_ + x] = v * scale;
                }
            }
        }
    }
}

// ================= launch =================
extern "C" void kernel_launch(void* const* d_in, const int* in_sizes, int n_in,
                              void* d_out, int out_size)
{
    const float* in1 = (const float*)d_in[0];
    const float* in2 = (const float*)d_in[1];
    float* out = (float*)d_out;

    cudaFuncSetAttribute(corr_hmma, cudaFuncAttributeMaxDynamicSharedMemorySize, SMEM_REQ);

    prep_a<<<BB * HH, 128>>>(in1);
    prep_b<<<BB * HH, 128>>>(in2);
    corr_hmma<<<BB * HH, 384, SMEM_REQ>>>(out);
}

// round 6
// speedup vs baseline: 3.5638x; 1.2666x over previous
#include <cuda_runtime.h>
#include <cuda_fp16.h>
#include <cstdint>

// ---------------- problem constants ----------------
#define BB   8
#define CCH  256
#define HH   64
#define WW   96
#define ND   21
#define NDD  441
#define HW_  6144            // HH*WW

// ---------------- fp16 swizzled images ----------------
// layout: element (row r, k) at  r*512 + ((k>>3 ^ (r&7))*16) + (k&7)*2
#define A_IMG 49152          // 96 rows * 512 B
#define B_IMG 69632          // 136 rows * 512 B

__device__ __align__(16) unsigned char g_A[(size_t)BB * HH * A_IMG];  // 25.2 MB
__device__ __align__(16) unsigned char g_B[(size_t)BB * HH * B_IMG];  // 35.7 MB

// ---------------- main-kernel smem layout (relative to 1024-aligned base) ----
#define SM_A    0
#define SM_B0   49152
#define SM_B1   118784
#define SM_RED  188416       // 6 m-tiles * 28 regs * 32 lanes * 4B = 21504
#define SMEM_REQ (209920 + 1024)

// ---------------- ptx helpers (baseline PTX only) -------
__device__ __forceinline__ void cp_async16(uint32_t s, const void* g) {
    asm volatile("cp.async.cg.shared.global [%0], [%1], 16;\n" :: "r"(s), "l"(g));
}
__device__ __forceinline__ void cp_commit() {
    asm volatile("cp.async.commit_group;" ::: "memory");
}
template<int N> __device__ __forceinline__ void cp_wait() {
    asm volatile("cp.async.wait_group %0;" :: "n"(N) : "memory");
}
__device__ __forceinline__ void ldsm4(uint32_t* r, uint32_t a) {
    asm volatile("ldmatrix.sync.aligned.m8n8.x4.shared.b16 {%0,%1,%2,%3}, [%4];"
                 : "=r"(r[0]), "=r"(r[1]), "=r"(r[2]), "=r"(r[3]) : "r"(a));
}
__device__ __forceinline__ void ldsm2(uint32_t* r, uint32_t a) {
    asm volatile("ldmatrix.sync.aligned.m8n8.x2.shared.b16 {%0,%1}, [%2];"
                 : "=r"(r[0]), "=r"(r[1]) : "r"(a));
}
__device__ __forceinline__ void mma16816(float* d, const uint32_t* a, const uint32_t* b) {
    asm volatile("mma.sync.aligned.m16n8k16.row.col.f32.f16.f16.f32 "
                 "{%0,%1,%2,%3}, {%4,%5,%6,%7}, {%8,%9}, {%0,%1,%2,%3};"
                 : "+f"(d[0]), "+f"(d[1]), "+f"(d[2]), "+f"(d[3])
                 : "r"(a[0]), "r"(a[1]), "r"(a[2]), "r"(a[3]), "r"(b[0]), "r"(b[1]));
}

// ================= fused prepass: A and B fp16 swizzled images per (b,y) =====
// 256 threads: warp -> 8 channel-rows, lane -> x. Coalesced loads, no div/mod.
__global__ __launch_bounds__(256) void prep_fused(const float* __restrict__ in1,
                                                  const float* __restrict__ in2) {
    __shared__ float raw[64][97];
    int bid = blockIdx.x;
    int y = bid & 63, b = bid >> 6;
    int tid = threadIdx.x, w = tid >> 5, lane = tid & 31;
    unsigned char* imgA = g_A + (size_t)bid * A_IMG;
    unsigned char* imgB = g_B + (size_t)bid * B_IMG;

    // ---- tensor 0: in1 -> A image ----
    for (int q = 0; q < 4; q++) {
        __syncthreads();
        #pragma unroll
        for (int rr = 0; rr < 8; rr++) {
            int c = w * 8 + rr;
            const float* src = in1 + (((size_t)b * CCH + q * 64 + c) * HH + y) * WW;
            #pragma unroll
            for (int m = 0; m < 3; m++)
                raw[c][lane + 32 * m] = src[lane + 32 * m];
        }
        __syncthreads();
        #pragma unroll
        for (int it = 0; it < 3; it++) {
            int u = tid + it * 256;          // u < 768
            int r = u >> 3, kl = u & 7;
            int ku = q * 8 + kl;
            uint32_t h[4];
            #pragma unroll
            for (int j = 0; j < 4; j++) {
                __half2 v = __floats2half2_rn(raw[kl * 8 + 2 * j][r],
                                              raw[kl * 8 + 2 * j + 1][r]);
                h[j] = *reinterpret_cast<uint32_t*>(&v);
            }
            int off = r * 512 + ((ku ^ (r & 7)) << 4);
            *reinterpret_cast<uint4*>(imgA + off) = make_uint4(h[0], h[1], h[2], h[3]);
        }
    }

    // ---- tensor 1: in2 -> padded B image (same y slot) ----
    for (int q = 0; q < 4; q++) {
        __syncthreads();
        #pragma unroll
        for (int rr = 0; rr < 8; rr++) {
            int c = w * 8 + rr;
            const float* src = in2 + (((size_t)b * CCH + q * 64 + c) * HH + y) * WW;
            #pragma unroll
            for (int m = 0; m < 3; m++)
                raw[c][lane + 32 * m] = src[lane + 32 * m];
        }
        __syncthreads();
        #pragma unroll
        for (int it = 0; it < 5; it++) {
            int u = tid + it * 256;          // u < 1088 (last iter partial)
            if (u < 1088) {
                int r = u >> 3, kl = u & 7;  // r = x' slot 0..135
                int ku = q * 8 + kl;
                int xs = r - 20;
                bool ok = (unsigned)xs < 96u;
                uint32_t h[4];
                #pragma unroll
                for (int j = 0; j < 4; j++) {
                    float lo = ok ? raw[kl * 8 + 2 * j][xs]     : 0.0f;
                    float hi = ok ? raw[kl * 8 + 2 * j + 1][xs] : 0.0f;
                    __half2 v = __floats2half2_rn(lo, hi);
                    h[j] = *reinterpret_cast<uint32_t*>(&v);
                }
                int off = r * 512 + ((ku ^ (r & 7)) << 4);
                *reinterpret_cast<uint4*>(imgB + off) = make_uint4(h[0], h[1], h[2], h[3]);
            }
        }
    }
}

// ================= main kernel: banded HMMA GEMM per (b,y) ====================
__global__ __launch_bounds__(384, 1) void corr_hmma(float* __restrict__ out) {
    extern __shared__ __align__(16) unsigned char smraw[];
    uint32_t SB = ((uint32_t)__cvta_generic_to_shared(smraw) + 1023u) & ~1023u;

    int bid = blockIdx.x;
    int y = bid & 63, b = bid >> 6;
    int tid = threadIdx.x, w = tid >> 5, lane = tid & 31;
    int mt = w % 6;          // m16 tile: x in [16mt, 16mt+16)
    int kh = w / 6;          // k-half: channels [128kh, 128kh+128)
    int g = lane >> 2, t = lane & 3;

    // ---- valid dy list ----
    int vlist[ND]; int nv = 0;
    #pragma unroll
    for (int d = 0; d < ND; d++) {
        int y2 = y - 20 + 2 * d;
        if ((unsigned)y2 < (unsigned)HH) vlist[nv++] = d;
    }

    // ---- prologue staging: A (full) + B row vlist[0] ----
    const unsigned char* imgA = g_A + (size_t)bid * A_IMG;
    for (int i = tid; i < 3072; i += 384)
        cp_async16(SB + SM_A + i * 16, imgA + i * 16);
    {
        int y2 = y - 20 + 2 * vlist[0];
        const unsigned char* img = g_B + (size_t)(b * HH + y2) * B_IMG;
        for (int i = tid; i < 4352; i += 384)
            cp_async16(SB + SM_B0 + i * 16, img + i * 16);
    }
    cp_commit();

    // ---- zero invalid-dy output slices (overlaps prologue cp.async) ----
    #pragma unroll 1
    for (int d = 0; d < ND; d++) {
        int y2 = y - 20 + 2 * d;
        if ((unsigned)y2 >= (unsigned)HH) {
            for (int i = tid; i < ND * WW; i += 384) {
                int dj = i / WW, x = i - dj * WW;
                out[(((size_t)b * NDD + d * ND + dj) * HH + y) * WW + x] = 0.0f;
            }
        }
    }

    // ---- per-lane ldmatrix address precompute ----
    uint32_t arow  = 16u * mt + (lane & 7) + 8u * ((lane >> 3) & 1);
    uint32_t abase = SB + SM_A + arow * 512u;
    uint32_t ar7   = arow & 7u;
    uint32_t akoff = (uint32_t)(lane >> 4);           // +0 / +1 k-unit
    uint32_t bkoff = (uint32_t)((lane >> 3) & 1);

    uint32_t brow512[4], br7[4];
    #pragma unroll
    for (int p = 0; p < 3; p++) {
        uint32_t br = 8u * (2u * mt + 2u * p + (uint32_t)(lane >> 4)) + (lane & 7);
        brow512[p] = br * 512u;
        br7[p] = br & 7u;
    }
    {
        uint32_t br = 8u * (2u * mt + 6u) + (lane & 7);
        brow512[3] = br * 512u;
        br7[3] = br & 7u;
    }

    uint32_t redb = SB + SM_RED + (uint32_t)mt * 3584u;
    const float scale = 1.0f / 256.0f;

    // ---- main loop over valid dy rows ----
    #pragma unroll 1
    for (int vi = 0; vi < nv; vi++) {
        // stage next row into other buffer; wait for current
        if (vi + 1 < nv) {
            int y2n = y - 20 + 2 * vlist[vi + 1];
            const unsigned char* img = g_B + (size_t)(b * HH + y2n) * B_IMG;
            uint32_t dst = SB + (((vi + 1) & 1) ? SM_B1 : SM_B0);
            for (int i = tid; i < 4352; i += 384)
                cp_async16(dst + i * 16, img + i * 16);
            cp_commit();
            cp_wait<1>();
        } else {
            cp_wait<0>();
        }
        __syncthreads();

        uint32_t SBB = SB + ((vi & 1) ? SM_B1 : SM_B0);

        float acc[7][4];
        #pragma unroll
        for (int jj = 0; jj < 7; jj++)
            #pragma unroll
            for (int r = 0; r < 4; r++) acc[jj][r] = 0.0f;

        #pragma unroll
        for (int ks = 0; ks < 8; ks++) {
            uint32_t aku = (uint32_t)(kh * 16 + 2 * ks) + akoff;
            uint32_t a[4];
            ldsm4(a, abase + ((aku ^ ar7) << 4));

            uint32_t bku = (uint32_t)(kh * 16 + 2 * ks) + bkoff;
            uint32_t bfr[7][2];
            #pragma unroll
            for (int p = 0; p < 3; p++)
                ldsm4(&bfr[2 * p][0], SBB + brow512[p] + ((bku ^ br7[p]) << 4));
            ldsm2(&bfr[6][0], SBB + brow512[3] + ((bku ^ br7[3]) << 4));

            #pragma unroll
            for (int jj = 0; jj < 7; jj++)
                mma16816(acc[jj], a, bfr[jj]);
        }

        // ---- split-K reduce through smem scratch ----
        if (kh == 0) {
            #pragma unroll
            for (int jj = 0; jj < 7; jj++)
                #pragma unroll
                for (int r = 0; r < 4; r++)
                    asm volatile("st.shared.f32 [%0], %1;"
                                 :: "r"(redb + (uint32_t)((jj * 4 + r) * 128 + lane * 4)),
                                    "f"(acc[jj][r]) : "memory");
        }
        __syncthreads();
        if (kh == 1) {
            #pragma unroll
            for (int jj = 0; jj < 7; jj++)
                #pragma unroll
                for (int r = 0; r < 4; r++) {
                    float p;
                    asm volatile("ld.shared.f32 %0, [%1];"
                                 : "=f"(p)
                                 : "r"(redb + (uint32_t)((jj * 4 + r) * 128 + lane * 4)));
                    acc[jj][r] += p;
                }

            // ---- band extraction epilogue ----
            int dyi = vlist[vi];
            size_t obase = (((size_t)b * NDD + dyi * ND) * HH + y) * WW;
            #pragma unroll
            for (int jj = 0; jj < 7; jj++) {
                #pragma unroll
                for (int rh = 0; rh < 2; rh++) {
                    int di = 4 * jj - 4 * rh + t - (g >> 1);
                    float v = (g & 1) ? acc[jj][2 * rh + 1] : acc[jj][2 * rh];
                    int x = 16 * mt + g + 8 * rh;
                    if ((unsigned)di <= 20u)
                        out[obase + (size_t)di * HW_ + x] = v * scale;
                }
            }
        }
    }
}

// ================= launch =================
extern "C" void kernel_launch(void* const* d_in, const int* in_sizes, int n_in,
                              void* d_out, int out_size)
{
    const float* in1 = (const float*)d_in[0];
    const float* in2 = (const float*)d_in[1];
    float* out = (float*)d_out;

    cudaFuncSetAttribute(corr_hmma, cudaFuncAttributeMaxDynamicSharedMemorySize, SMEM_REQ);

    prep_fused<<<BB * HH, 256>>>(in1, in2);
    corr_hmma<<<BB * HH, 384, SMEM_REQ>>>(out);
}